// round 3
// baseline (speedup 1.0000x reference)
#include <cuda_runtime.h>
#include <math.h>

// Problem constants: n=1, t=3, c=64, h=w=32
#define HW 1024

// ---------------- static scratch (no allocations allowed) ----------------
__device__ float g_extra [460 * HW];
__device__ float g_b192a [192 * HW];
__device__ float g_value [192 * HW];
__device__ float g_vperm [24 * HW * 8];     // [(m*3+l)][pix][d]
__device__ float g_b64a  [64 * HW];
__device__ float g_b64b  [64 * HW];
__device__ float g_so    [1728 * HW];
__device__ float g_aw    [7776 * HW];
__device__ float g_awsoft[7776 * HW];       // [q][m][324] compact
__device__ float g_attn  [192 * HW];
__device__ float g_part  [16 * 192 * HW];   // split-K partials

// flow channel base in g_extra for (ti, l); -1 = zero flow
__constant__ int c_flowtbl[9] = {-1, 448, 450, 452, -1, 454, 458, 456, -1};
__constant__ int c_srcfrm[6]  = {1, 2, 0, 2, 1, 0};
__constant__ int c_flowbase[6]= {448, 450, 452, 454, 456, 458};

// ---------------- flow composition ----------------
__device__ __forceinline__ void bilin2(const float* __restrict__ img, float px, float py,
                                       float& ox, float& oy) {
    float fx = floorf(px), fy = floorf(py);
    int x0 = (int)fx, y0 = (int)fy;
    float ax = px - fx, ay = py - fy;
    ox = 0.f; oy = 0.f;
    #pragma unroll
    for (int dy = 0; dy < 2; dy++)
        #pragma unroll
        for (int dx = 0; dx < 2; dx++) {
            int xi = x0 + dx, yi = y0 + dy;
            if (xi >= 0 && xi < 32 && yi >= 0 && yi < 32) {
                float w = (dx ? ax : 1.f - ax) * (dy ? ay : 1.f - ay);
                int o = yi * 32 + xi;
                ox += w * img[o];
                oy += w * img[HW + o];
            }
        }
}

__global__ void k_flows(const float* __restrict__ f1, const float* __restrict__ f2,
                        const float* __restrict__ ff1, const float* __restrict__ ff2) {
    int pix = blockIdx.x * blockDim.x + threadIdx.x;
    if (pix >= HW) return;
    int y = pix >> 5, x = pix & 31;
    float f1x = f1[pix],  f1y = f1[HW + pix];
    float ff2x = ff2[pix], ff2y = ff2[HW + pix];
    float wf2x, wf2y;   bilin2(f2,  (float)x + f1x,  (float)y + f1y,  wf2x, wf2y);
    float wff1x, wff1y; bilin2(ff1, (float)x + ff2x, (float)y + ff2y, wff1x, wff1y);
    g_extra[448*HW + pix] = f1x;            g_extra[449*HW + pix] = f1y;
    g_extra[450*HW + pix] = f1x + wf2x;     g_extra[451*HW + pix] = f1y + wf2y;
    g_extra[452*HW + pix] = ff1[pix];       g_extra[453*HW + pix] = ff1[HW + pix];
    g_extra[454*HW + pix] = f2[pix];        g_extra[455*HW + pix] = f2[HW + pix];
    g_extra[456*HW + pix] = ff2x;           g_extra[457*HW + pix] = ff2y;
    g_extra[458*HW + pix] = ff2x + wff1x;   g_extra[459*HW + pix] = ff2y + wff1y;
}

// ---------------- warp 6 frames + copy frame0 into extra ----------------
__global__ void k_warp(const float* __restrict__ x) {
    int gid = blockIdx.x * blockDim.x + threadIdx.x;   // 7 * 1024
    int j = gid >> 10, pix = gid & 1023;
    if (j >= 7) return;
    if (j == 6) {
        #pragma unroll 4
        for (int ch = 0; ch < 64; ch++)
            g_extra[ch * HW + pix] = x[ch * HW + pix];
        return;
    }
    int y = pix >> 5, xc = pix & 31;
    int fb = c_flowbase[j];
    float fx = g_extra[fb * HW + pix], fy = g_extra[(fb + 1) * HW + pix];
    float px = (float)xc + fx, py = (float)y + fy;
    float flx = floorf(px), fly = floorf(py);
    int x0 = (int)flx, y0 = (int)fly;
    float ax = px - flx, ay = py - fly;
    int   toff[4]; float tw[4];
    #pragma unroll
    for (int dy = 0; dy < 2; dy++)
        #pragma unroll
        for (int dx = 0; dx < 2; dx++) {
            int xi = x0 + dx, yi = y0 + dy, t = dy * 2 + dx;
            bool ok = (xi >= 0 && xi < 32 && yi >= 0 && yi < 32);
            toff[t] = ok ? (yi * 32 + xi) : 0;
            tw[t] = ok ? (dx ? ax : 1.f - ax) * (dy ? ay : 1.f - ay) : 0.f;
        }
    const float* src = x + c_srcfrm[j] * 64 * HW;
    int dst = 64 * (1 + j);
    for (int ch = 0; ch < 64; ch++) {
        const float* im = src + ch * HW;
        float v = tw[0]*im[toff[0]] + tw[1]*im[toff[1]] + tw[2]*im[toff[2]] + tw[3]*im[toff[3]];
        g_extra[(dst + ch) * HW + pix] = v;
    }
}

// ---------------- generic 3x3 SAME conv, implicit GEMM ----------------
// tile: 64 out-ch x (4 rows x 32 cols), 256 threads, 8co x 4px per thread,
// cin chunked by 8, optional split-K over blockIdx.z (partials -> k_finalize)
__global__ void __launch_bounds__(256, 2)
k_conv(const float* __restrict__ in, const float* __restrict__ wt,
       const float* __restrict__ bias, float* __restrict__ out,
       const float* __restrict__ residual,
       int Cin, int Cout, int act, int nz, int total_chunks, int cpz) {
    __shared__ float si[8 * 6 * 34];      // [ci][row(6)][col(34)]
    __shared__ float sw[8 * 9 * 65];      // [(ci*9+k)][co(64, pad 65)]
    int tid = threadIdx.x;
    int col = tid & 31, cogrp = tid >> 5;
    int co_base = blockIdx.x * 64;
    int r_base = blockIdx.y * 4;
    int z = blockIdx.z;
    int c0 = z * cpz;
    int c1 = min(total_chunks, c0 + cpz);

    float acc[8][4];
    #pragma unroll
    for (int u = 0; u < 8; u++)
        #pragma unroll
        for (int r = 0; r < 4; r++) acc[u][r] = 0.f;

    for (int ck = c0; ck < c1; ck++) {
        int ci0 = ck * 8;
        // input tile with halo (zero pad)
        for (int li = tid; li < 8 * 6 * 34; li += 256) {
            int ci = li / 204; int rem = li - ci * 204;
            int rr = rem / 34; int cc = rem - rr * 34;
            int gy = r_base - 1 + rr, gx = cc - 1, gci = ci0 + ci;
            float v = 0.f;
            if (gci < Cin && gy >= 0 && gy < 32 && gx >= 0 && gx < 32)
                v = in[gci * HW + gy * 32 + gx];
            si[li] = v;
        }
        // weights: global coalesced (72-float runs per co), smem stride 65 (conflict-free)
        for (int li = tid; li < 64 * 72; li += 256) {
            int co = li / 72; int rem = li - co * 72;
            int ci = rem / 9; int k = rem - ci * 9;
            int gco = co_base + co, gci = ci0 + ci;
            float v = 0.f;
            if (gco < Cout && gci < Cin) v = wt[(gco * Cin + gci) * 9 + k];
            sw[(ci * 9 + k) * 65 + co] = v;
        }
        __syncthreads();
        #pragma unroll 2
        for (int ci = 0; ci < 8; ci++) {
            float iv[6][3];
            #pragma unroll
            for (int rr = 0; rr < 6; rr++)
                #pragma unroll
                for (int cc = 0; cc < 3; cc++)
                    iv[rr][cc] = si[(ci * 6 + rr) * 34 + col + cc];
            #pragma unroll
            for (int ky = 0; ky < 3; ky++)
                #pragma unroll
                for (int kx = 0; kx < 3; kx++) {
                    const float* wp = &sw[(ci * 9 + ky * 3 + kx) * 65 + cogrp * 8];
                    float wv[8];
                    #pragma unroll
                    for (int u = 0; u < 8; u++) wv[u] = wp[u];
                    #pragma unroll
                    for (int u = 0; u < 8; u++)
                        #pragma unroll
                        for (int r = 0; r < 4; r++)
                            acc[u][r] += wv[u] * iv[r + ky][kx];
                }
        }
        __syncthreads();
    }

    if (nz == 1) {
        #pragma unroll
        for (int u = 0; u < 8; u++) {
            int co = co_base + cogrp * 8 + u;
            if (co < Cout) {
                float b = bias[co];
                #pragma unroll
                for (int r = 0; r < 4; r++) {
                    int oi = co * HW + (r_base + r) * 32 + col;
                    float v = acc[u][r] + b;
                    if (act) v = (v >= 0.f) ? v : 0.1f * v;
                    if (residual) v += residual[oi];
                    out[oi] = v;
                }
            }
        }
    } else {
        float* po = out + (size_t)z * Cout * HW;
        #pragma unroll
        for (int u = 0; u < 8; u++) {
            int co = co_base + cogrp * 8 + u;
            if (co < Cout)
                #pragma unroll
                for (int r = 0; r < 4; r++)
                    po[co * HW + (r_base + r) * 32 + col] = acc[u][r];
        }
    }
}

__global__ void k_finalize(const float* __restrict__ part, const float* __restrict__ bias,
                           float* __restrict__ out, const float* __restrict__ residual,
                           int Cout, int nz, int act) {
    int idx = blockIdx.x * blockDim.x + threadIdx.x;
    if (idx >= Cout * HW) return;
    int ch = idx >> 10;
    float v = 0.f;
    for (int z = 0; z < nz; z++) v += part[(size_t)z * Cout * HW + idx];
    v += bias[ch];
    if (act) v = (v >= 0.f) ? v : 0.1f * v;
    if (residual) v += residual[idx];
    out[idx] = v;
}

// ---------------- value permute: [l*64+m*8+d][pix] -> [(m*3+l)][pix][d] ----------------
__global__ void k_vperm() {
    int idx = blockIdx.x * blockDim.x + threadIdx.x;   // 24*1024*8
    if (idx >= 24 * HW * 8) return;
    int ml = idx >> 13; int rem = idx & 8191;
    int pix = rem >> 3; int d = rem & 7;
    int m = ml / 3, l = ml - m * 3;
    g_vperm[idx] = g_value[(l * 64 + m * 8 + d) * HW + pix];
}

// ---------------- softmax over 324 per (q, m), compact output ----------------
__global__ void k_softmax() {
    int b = blockIdx.x;                 // 24 = ti*8+m
    int ti = b >> 3, m = b & 7;
    int p = blockIdx.y * blockDim.x + threadIdx.x;   // gridDim.y = 4
    if (p >= HW) return;
    int chbase = ti * 2592 + m * 324;
    float mx = -1e30f, sm = 0.f;
    for (int j = 0; j < 324; j++) {
        float v = g_aw[(chbase + j) * HW + p];
        float nm = fmaxf(mx, v);
        sm = sm * __expf(mx - nm) + __expf(v - nm);
        mx = nm;
    }
    float inv = 1.f / sm;
    int ob = ((ti * HW + p) * 8 + m) * 324;
    for (int j = 0; j < 324; j++) {
        float v = g_aw[(chbase + j) * HW + p];
        g_awsoft[ob + j] = __expf(v - mx) * inv;
    }
}

// ---------------- deformable attention sampling: one warp per (q, m) ----------------
__global__ void __launch_bounds__(256) k_sample() {
    int q = blockIdx.x;                 // 3072
    int m = threadIdx.x >> 5;
    int lane = threadIdx.x & 31;
    int ti = q >> 10, pix = q & 1023;
    int y = pix >> 5, x = pix & 31;

    float acc[8];
    #pragma unroll
    for (int d = 0; d < 8; d++) acc[d] = 0.f;

    for (int s = lane; s < 324; s += 32) {
        int l = s / 108; int rem = s - l * 108;
        int p = rem / 9;  int k = rem - p * 9;
        int soch = ((ti * 8 + m) * 3 + l) * 24 + p * 2;
        float ox = g_so[soch * HW + pix];
        float oy = g_so[(soch + 1) * HW + pix];
        int fb = c_flowtbl[ti * 3 + l];
        if (fb >= 0) {
            ox += g_extra[fb * HW + pix];
            oy += g_extra[(fb + 1) * HW + pix];
        }
        float px = (float)x + ox + (float)(k / 3 - 1);
        float py = (float)y + oy + (float)(k % 3 - 1);
        float aw = g_awsoft[(q * 8 + m) * 324 + s];
        float flx = floorf(px), fly = floorf(py);
        int x0 = (int)flx, y0 = (int)fly;
        float ax = px - flx, ay = py - fly;
        const float* vb = g_vperm + (m * 3 + l) * (HW * 8);
        #pragma unroll
        for (int dy = 0; dy < 2; dy++)
            #pragma unroll
            for (int dx = 0; dx < 2; dx++) {
                int xi = x0 + dx, yi = y0 + dy;
                if (xi >= 0 && xi < 32 && yi >= 0 && yi < 32) {
                    float wgt = aw * (dx ? ax : 1.f - ax) * (dy ? ay : 1.f - ay);
                    const float4* vp = (const float4*)(vb + (yi * 32 + xi) * 8);
                    float4 a = vp[0], bb = vp[1];
                    acc[0] += wgt * a.x;  acc[1] += wgt * a.y;
                    acc[2] += wgt * a.z;  acc[3] += wgt * a.w;
                    acc[4] += wgt * bb.x; acc[5] += wgt * bb.y;
                    acc[6] += wgt * bb.z; acc[7] += wgt * bb.w;
                }
            }
    }
    #pragma unroll
    for (int d = 0; d < 8; d++)
        #pragma unroll
        for (int off = 16; off > 0; off >>= 1)
            acc[d] += __shfl_xor_sync(0xffffffffu, acc[d], off);
    if (lane == 0) {
        int ob = (ti * 64 + m * 8) * HW + pix;
        #pragma unroll
        for (int d = 0; d < 8; d++) g_attn[ob + d * HW] = acc[d];
    }
}

// ---------------- host side ----------------
static void launch_conv(const float* in, const float* wt, const float* bs,
                        float* out, const float* res, float* part,
                        int Cin, int Cout, int act, int nz) {
    int chunks = (Cin + 7) / 8;
    int cpz = (chunks + nz - 1) / nz;
    dim3 grid((Cout + 63) / 64, 8, nz);
    if (nz == 1) {
        k_conv<<<grid, 256>>>(in, wt, bs, out, res, Cin, Cout, act, 1, chunks, cpz);
    } else {
        k_conv<<<grid, 256>>>(in, wt, nullptr, part, nullptr, Cin, Cout, 0, nz, chunks, cpz);
        k_finalize<<<(Cout * HW + 255) / 256, 256>>>(part, bs, out, res, Cout, nz, act);
    }
}

extern "C" void kernel_launch(void* const* d_in, const int* in_sizes, int n_in,
                              void* d_out, int out_size) {
    const float* x   = (const float*)d_in[0];
    const float* f1  = (const float*)d_in[1];
    const float* f2  = (const float*)d_in[2];
    const float* ff1 = (const float*)d_in[3];
    const float* ff2 = (const float*)d_in[4];
    const float* vp0w = (const float*)d_in[5];  const float* vp0b = (const float*)d_in[6];
    const float* vp1w = (const float*)d_in[7];  const float* vp1b = (const float*)d_in[8];
    const float* so0w = (const float*)d_in[9];  const float* so0b = (const float*)d_in[10];
    const float* so1w = (const float*)d_in[11]; const float* so1b = (const float*)d_in[12];
    const float* so2w = (const float*)d_in[13]; const float* so2b = (const float*)d_in[14];
    const float* so3w = (const float*)d_in[15]; const float* so3b = (const float*)d_in[16];
    const float* aw0w = (const float*)d_in[17]; const float* aw0b = (const float*)d_in[18];
    const float* aw1w = (const float*)d_in[19]; const float* aw1b = (const float*)d_in[20];
    const float* aw2w = (const float*)d_in[21]; const float* aw2b = (const float*)d_in[22];
    const float* aw3w = (const float*)d_in[23]; const float* aw3b = (const float*)d_in[24];
    const float* op0w = (const float*)d_in[25]; const float* op0b = (const float*)d_in[26];
    const float* op1w = (const float*)d_in[27]; const float* op1b = (const float*)d_in[28];

    float *extra, *b192a, *value, *b64a, *b64b, *so, *aw, *attn, *part;
    cudaGetSymbolAddress((void**)&extra, g_extra);
    cudaGetSymbolAddress((void**)&b192a, g_b192a);
    cudaGetSymbolAddress((void**)&value, g_value);
    cudaGetSymbolAddress((void**)&b64a,  g_b64a);
    cudaGetSymbolAddress((void**)&b64b,  g_b64b);
    cudaGetSymbolAddress((void**)&so,    g_so);
    cudaGetSymbolAddress((void**)&aw,    g_aw);
    cudaGetSymbolAddress((void**)&attn,  g_attn);
    cudaGetSymbolAddress((void**)&part,  g_part);

    // 1. flow composition + extra flow channels
    k_flows<<<4, 256>>>(f1, f2, ff1, ff2);
    // 2. six flow-warped frames + frame0 copy into extra
    k_warp<<<28, 256>>>(x);
    // 3. value projection (192->192 lrelu, 192->192)
    launch_conv(x,     vp0w, vp0b, b192a, nullptr, part, 192, 192, 1, 6);
    launch_conv(b192a, vp1w, vp1b, value, nullptr, part, 192, 192, 0, 6);
    k_vperm<<<(24 * HW * 8 + 255) / 256, 256>>>();
    // 4. sampling-offset head
    launch_conv(extra, so0w, so0b, b64a, nullptr, part, 460, 64,   1, 15);
    launch_conv(b64a,  so1w, so1b, b64b, nullptr, part, 64,  64,   1, 8);
    launch_conv(b64b,  so2w, so2b, b64a, nullptr, part, 64,  64,   1, 8);
    launch_conv(b64a,  so3w, so3b, so,   nullptr, part, 64,  1728, 0, 1);
    // 5. attention-weight head
    launch_conv(extra, aw0w, aw0b, b64a, nullptr, part, 460, 64,   1, 15);
    launch_conv(b64a,  aw1w, aw1b, b64b, nullptr, part, 64,  64,   1, 8);
    launch_conv(b64b,  aw2w, aw2b, b64a, nullptr, part, 64,  64,   1, 8);
    launch_conv(b64a,  aw3w, aw3b, aw,   nullptr, part, 64,  7776, 0, 1);
    // 6. softmax (compact [q][m][324])
    { dim3 g(24, 4); k_softmax<<<g, 256>>>(); }
    // 7. deformable attention sampling
    k_sample<<<3072, 256>>>();
    // 8. output projection + residual
    launch_conv(attn,  op0w, op0b, b192a,          nullptr, part, 192, 192, 1, 6);
    launch_conv(b192a, op1w, op1b, (float*)d_out,  x,       part, 192, 192, 0, 6);
}

// round 7
// speedup vs baseline: 1.0719x; 1.0719x over previous
#include <cuda_runtime.h>
#include <math.h>

// Problem constants: n=1, t=3, c=64, h=w=32
#define HW 1024

// ---------------- static scratch (no allocations allowed) ----------------
__device__ float g_extra [460 * HW];
__device__ float g_b192a [192 * HW];
__device__ float g_value [192 * HW];
__device__ float g_vperm [24 * HW * 8];     // [(m*3+l)][pix][d]
__device__ float g_b64a  [64 * HW];
__device__ float g_b64b  [64 * HW];
__device__ float g_so    [1728 * HW];
__device__ float g_aw    [7776 * HW];
__device__ float g_awsoft[7776 * HW];       // [q][m][324] compact
__device__ float g_attn  [192 * HW];
__device__ float g_part  [16 * 192 * HW];   // split-K partials

// flow channel base in g_extra for (ti, l); -1 = zero flow
__constant__ int c_flowtbl[9] = {-1, 448, 450, 452, -1, 454, 458, 456, -1};
__constant__ int c_srcfrm[6]  = {1, 2, 0, 2, 1, 0};
__constant__ int c_flowbase[6]= {448, 450, 452, 454, 456, 458};

// ---------------- f32x2 packed-FMA helpers (sm_103a FFMA2) ----------------
__device__ __forceinline__ unsigned long long pack2(float v) {
    unsigned long long r;
    asm("mov.b64 %0, {%1, %1};" : "=l"(r) : "f"(v));
    return r;
}
__device__ __forceinline__ void ffma2(unsigned long long& d,
                                      unsigned long long a, unsigned long long b) {
    asm("fma.rn.f32x2 %0, %1, %2, %0;" : "+l"(d) : "l"(a), "l"(b));
}
__device__ __forceinline__ void unpack2(unsigned long long v, float& lo, float& hi) {
    asm("mov.b64 {%0, %1}, %2;" : "=f"(lo), "=f"(hi) : "l"(v));
}

// ---------------- flow composition ----------------
__device__ __forceinline__ void bilin2(const float* __restrict__ img, float px, float py,
                                       float& ox, float& oy) {
    float fx = floorf(px), fy = floorf(py);
    int x0 = (int)fx, y0 = (int)fy;
    float ax = px - fx, ay = py - fy;
    ox = 0.f; oy = 0.f;
    #pragma unroll
    for (int dy = 0; dy < 2; dy++)
        #pragma unroll
        for (int dx = 0; dx < 2; dx++) {
            int xi = x0 + dx, yi = y0 + dy;
            if (xi >= 0 && xi < 32 && yi >= 0 && yi < 32) {
                float w = (dx ? ax : 1.f - ax) * (dy ? ay : 1.f - ay);
                int o = yi * 32 + xi;
                ox += w * img[o];
                oy += w * img[HW + o];
            }
        }
}

__global__ void k_flows(const float* __restrict__ f1, const float* __restrict__ f2,
                        const float* __restrict__ ff1, const float* __restrict__ ff2) {
    int pix = blockIdx.x * blockDim.x + threadIdx.x;
    if (pix >= HW) return;
    int y = pix >> 5, x = pix & 31;
    float f1x = f1[pix],  f1y = f1[HW + pix];
    float ff2x = ff2[pix], ff2y = ff2[HW + pix];
    float wf2x, wf2y;   bilin2(f2,  (float)x + f1x,  (float)y + f1y,  wf2x, wf2y);
    float wff1x, wff1y; bilin2(ff1, (float)x + ff2x, (float)y + ff2y, wff1x, wff1y);
    g_extra[448*HW + pix] = f1x;            g_extra[449*HW + pix] = f1y;
    g_extra[450*HW + pix] = f1x + wf2x;     g_extra[451*HW + pix] = f1y + wf2y;
    g_extra[452*HW + pix] = ff1[pix];       g_extra[453*HW + pix] = ff1[HW + pix];
    g_extra[454*HW + pix] = f2[pix];        g_extra[455*HW + pix] = f2[HW + pix];
    g_extra[456*HW + pix] = ff2x;           g_extra[457*HW + pix] = ff2y;
    g_extra[458*HW + pix] = ff2x + wff1x;   g_extra[459*HW + pix] = ff2y + wff1y;
}

// ---------------- warp 6 frames + copy frame0 into extra ----------------
__global__ void k_warp(const float* __restrict__ x) {
    int gid = blockIdx.x * blockDim.x + threadIdx.x;   // 7 * 1024
    int j = gid >> 10, pix = gid & 1023;
    if (j >= 7) return;
    if (j == 6) {
        #pragma unroll 4
        for (int ch = 0; ch < 64; ch++)
            g_extra[ch * HW + pix] = x[ch * HW + pix];
        return;
    }
    int y = pix >> 5, xc = pix & 31;
    int fb = c_flowbase[j];
    float fx = g_extra[fb * HW + pix], fy = g_extra[(fb + 1) * HW + pix];
    float px = (float)xc + fx, py = (float)y + fy;
    float flx = floorf(px), fly = floorf(py);
    int x0 = (int)flx, y0 = (int)fly;
    float ax = px - flx, ay = py - fly;
    int   toff[4]; float tw[4];
    #pragma unroll
    for (int dy = 0; dy < 2; dy++)
        #pragma unroll
        for (int dx = 0; dx < 2; dx++) {
            int xi = x0 + dx, yi = y0 + dy, t = dy * 2 + dx;
            bool ok = (xi >= 0 && xi < 32 && yi >= 0 && yi < 32);
            toff[t] = ok ? (yi * 32 + xi) : 0;
            tw[t] = ok ? (dx ? ax : 1.f - ax) * (dy ? ay : 1.f - ay) : 0.f;
        }
    const float* src = x + c_srcfrm[j] * 64 * HW;
    int dst = 64 * (1 + j);
    for (int ch = 0; ch < 64; ch++) {
        const float* im = src + ch * HW;
        float v = tw[0]*im[toff[0]] + tw[1]*im[toff[1]] + tw[2]*im[toff[2]] + tw[3]*im[toff[3]];
        g_extra[(dst + ch) * HW + pix] = v;
    }
}

// ---------------- generic 3x3 SAME conv, implicit GEMM, FFMA2 ----------------
// tile: 64 out-ch x (4 rows x 32 cols), 256 threads, 8co x 4px per thread.
// Accumulators packed along co (pairs) -> weight pairs come straight out of
// LDS.128; input values packed {v,v} at point of use (CSE-able, remat-able).
__global__ void __launch_bounds__(256)
k_conv(const float* __restrict__ in, const float* __restrict__ wt,
       const float* __restrict__ bias, float* __restrict__ out,
       const float* __restrict__ residual,
       int Cin, int Cout, int act, int nz, int total_chunks, int cpz) {
    __shared__ float si[8 * 6 * 34];                      // [ci][row(6)][col(34)]
    __shared__ __align__(16) float sw[8 * 9 * 68];        // [(ci*9+k)][co pad 68]
    int tid = threadIdx.x;
    int col = tid & 31, cogrp = tid >> 5;
    int co_base = blockIdx.x * 64;
    int r_base = blockIdx.y * 4;
    int z = blockIdx.z;
    int c0 = z * cpz;
    int c1 = min(total_chunks, c0 + cpz);

    unsigned long long acc2[4][4];   // [co-pair p][row r], lo=co 2p, hi=co 2p+1
    #pragma unroll
    for (int p = 0; p < 4; p++)
        #pragma unroll
        for (int r = 0; r < 4; r++) acc2[p][r] = 0ULL;

    for (int ck = c0; ck < c1; ck++) {
        int ci0 = ck * 8;
        // input tile with halo (zero pad)
        for (int li = tid; li < 8 * 6 * 34; li += 256) {
            int ci = li / 204; int rem = li - ci * 204;
            int rr = rem / 34; int cc = rem - rr * 34;
            int gy = r_base - 1 + rr, gx = cc - 1, gci = ci0 + ci;
            float v = 0.f;
            if (gci < Cin && gy >= 0 && gy < 32 && gx >= 0 && gx < 32)
                v = in[gci * HW + gy * 32 + gx];
            si[li] = v;
        }
        // weights: global coalesced (72-float runs per co), smem stride 68 (16B-aligned rows)
        for (int li = tid; li < 64 * 72; li += 256) {
            int co = li / 72; int rem = li - co * 72;
            int ci = rem / 9; int k = rem - ci * 9;
            int gco = co_base + co, gci = ci0 + ci;
            float v = 0.f;
            if (gco < Cout && gci < Cin) v = wt[(gco * Cin + gci) * 9 + k];
            sw[(ci * 9 + k) * 68 + co] = v;
        }
        __syncthreads();
        for (int ci = 0; ci < 8; ci++) {
            float iv[6][3];
            #pragma unroll
            for (int rr = 0; rr < 6; rr++)
                #pragma unroll
                for (int cc = 0; cc < 3; cc++)
                    iv[rr][cc] = si[(ci * 6 + rr) * 34 + col + cc];
            #pragma unroll
            for (int ky = 0; ky < 3; ky++)
                #pragma unroll
                for (int kx = 0; kx < 3; kx++) {
                    // 8 weights for this (ci,k): 2x LDS.128 -> 4 f32x2 pairs (warp-uniform)
                    const float* wp = &sw[(ci * 9 + ky * 3 + kx) * 68 + cogrp * 8];
                    ulonglong2 wA = *(const ulonglong2*)wp;        // pairs (0,1),(2,3)
                    ulonglong2 wB = *(const ulonglong2*)(wp + 4);  // pairs (4,5),(6,7)
                    #pragma unroll
                    for (int r = 0; r < 4; r++) {
                        unsigned long long ivv = pack2(iv[r + ky][kx]);
                        ffma2(acc2[0][r], wA.x, ivv);
                        ffma2(acc2[1][r], wA.y, ivv);
                        ffma2(acc2[2][r], wB.x, ivv);
                        ffma2(acc2[3][r], wB.y, ivv);
                    }
                }
        }
        __syncthreads();
    }

    if (nz == 1) {
        #pragma unroll
        for (int p = 0; p < 4; p++) {
            int co0 = co_base + cogrp * 8 + p * 2;   // Cout always even -> pair never straddles
            if (co0 < Cout) {
                float b0 = bias[co0], b1 = bias[co0 + 1];
                #pragma unroll
                for (int r = 0; r < 4; r++) {
                    float lo, hi; unpack2(acc2[p][r], lo, hi);
                    int oi = co0 * HW + (r_base + r) * 32 + col;
                    float v0 = lo + b0, v1 = hi + b1;
                    if (act) { v0 = (v0 >= 0.f) ? v0 : 0.1f * v0;
                               v1 = (v1 >= 0.f) ? v1 : 0.1f * v1; }
                    if (residual) { v0 += residual[oi]; v1 += residual[oi + HW]; }
                    out[oi] = v0;
                    out[oi + HW] = v1;
                }
            }
        }
    } else {
        float* po = out + (size_t)z * Cout * HW;
        #pragma unroll
        for (int p = 0; p < 4; p++) {
            int co0 = co_base + cogrp * 8 + p * 2;
            if (co0 < Cout)
                #pragma unroll
                for (int r = 0; r < 4; r++) {
                    float lo, hi; unpack2(acc2[p][r], lo, hi);
                    int oi = co0 * HW + (r_base + r) * 32 + col;
                    po[oi] = lo;
                    po[oi + HW] = hi;
                }
        }
    }
}

__global__ void k_finalize(const float* __restrict__ part, const float* __restrict__ bias,
                           float* __restrict__ out, const float* __restrict__ residual,
                           int Cout, int nz, int act) {
    int idx = blockIdx.x * blockDim.x + threadIdx.x;
    if (idx >= Cout * HW) return;
    int ch = idx >> 10;
    float v = 0.f;
    for (int z = 0; z < nz; z++) v += part[(size_t)z * Cout * HW + idx];
    v += bias[ch];
    if (act) v = (v >= 0.f) ? v : 0.1f * v;
    if (residual) v += residual[idx];
    out[idx] = v;
}

// ---------------- value permute: [l*64+m*8+d][pix] -> [(m*3+l)][pix][d] ----------------
__global__ void k_vperm() {
    int idx = blockIdx.x * blockDim.x + threadIdx.x;   // 24*1024*8
    if (idx >= 24 * HW * 8) return;
    int ml = idx >> 13; int rem = idx & 8191;
    int pix = rem >> 3; int d = rem & 7;
    int m = ml / 3, l = ml - m * 3;
    g_vperm[idx] = g_value[(l * 64 + m * 8 + d) * HW + pix];
}

// ---------------- softmax over 324 per (q, m), compact output ----------------
__global__ void k_softmax() {
    int b = blockIdx.x;                 // 24 = ti*8+m
    int ti = b >> 3, m = b & 7;
    int p = blockIdx.y * blockDim.x + threadIdx.x;   // gridDim.y = 4
    if (p >= HW) return;
    int chbase = ti * 2592 + m * 324;
    float mx = -1e30f, sm = 0.f;
    for (int j = 0; j < 324; j++) {
        float v = g_aw[(chbase + j) * HW + p];
        float nm = fmaxf(mx, v);
        sm = sm * __expf(mx - nm) + __expf(v - nm);
        mx = nm;
    }
    float inv = 1.f / sm;
    int ob = ((ti * HW + p) * 8 + m) * 324;
    for (int j = 0; j < 324; j++) {
        float v = g_aw[(chbase + j) * HW + p];
        g_awsoft[ob + j] = __expf(v - mx) * inv;
    }
}

// ---------------- deformable attention sampling: one warp per (q, m) ----------------
__global__ void __launch_bounds__(256) k_sample() {
    int q = blockIdx.x;                 // 3072
    int m = threadIdx.x >> 5;
    int lane = threadIdx.x & 31;
    int ti = q >> 10, pix = q & 1023;
    int y = pix >> 5, x = pix & 31;

    float acc[8];
    #pragma unroll
    for (int d = 0; d < 8; d++) acc[d] = 0.f;

    for (int s = lane; s < 324; s += 32) {
        int l = s / 108; int rem = s - l * 108;
        int p = rem / 9;  int k = rem - p * 9;
        int soch = ((ti * 8 + m) * 3 + l) * 24 + p * 2;
        float ox = g_so[soch * HW + pix];
        float oy = g_so[(soch + 1) * HW + pix];
        int fb = c_flowtbl[ti * 3 + l];
        if (fb >= 0) {
            ox += g_extra[fb * HW + pix];
            oy += g_extra[(fb + 1) * HW + pix];
        }
        float px = (float)x + ox + (float)(k / 3 - 1);
        float py = (float)y + oy + (float)(k % 3 - 1);
        float aw = g_awsoft[(q * 8 + m) * 324 + s];
        float flx = floorf(px), fly = floorf(py);
        int x0 = (int)flx, y0 = (int)fly;
        float ax = px - flx, ay = py - fly;
        const float* vb = g_vperm + (m * 3 + l) * (HW * 8);
        #pragma unroll
        for (int dy = 0; dy < 2; dy++)
            #pragma unroll
            for (int dx = 0; dx < 2; dx++) {
                int xi = x0 + dx, yi = y0 + dy;
                if (xi >= 0 && xi < 32 && yi >= 0 && yi < 32) {
                    float wgt = aw * (dx ? ax : 1.f - ax) * (dy ? ay : 1.f - ay);
                    const float4* vp = (const float4*)(vb + (yi * 32 + xi) * 8);
                    float4 a = vp[0], bb = vp[1];
                    acc[0] += wgt * a.x;  acc[1] += wgt * a.y;
                    acc[2] += wgt * a.z;  acc[3] += wgt * a.w;
                    acc[4] += wgt * bb.x; acc[5] += wgt * bb.y;
                    acc[6] += wgt * bb.z; acc[7] += wgt * bb.w;
                }
            }
    }
    #pragma unroll
    for (int d = 0; d < 8; d++)
        #pragma unroll
        for (int off = 16; off > 0; off >>= 1)
            acc[d] += __shfl_xor_sync(0xffffffffu, acc[d], off);
    if (lane == 0) {
        int ob = (ti * 64 + m * 8) * HW + pix;
        #pragma unroll
        for (int d = 0; d < 8; d++) g_attn[ob + d * HW] = acc[d];
    }
}

// ---------------- host side ----------------
static void launch_conv(const float* in, const float* wt, const float* bs,
                        float* out, const float* res, float* part,
                        int Cin, int Cout, int act, int nz) {
    int chunks = (Cin + 7) / 8;
    int cpz = (chunks + nz - 1) / nz;
    dim3 grid((Cout + 63) / 64, 8, nz);
    if (nz == 1) {
        k_conv<<<grid, 256>>>(in, wt, bs, out, res, Cin, Cout, act, 1, chunks, cpz);
    } else {
        k_conv<<<grid, 256>>>(in, wt, nullptr, part, nullptr, Cin, Cout, 0, nz, chunks, cpz);
        k_finalize<<<(Cout * HW + 255) / 256, 256>>>(part, bs, out, res, Cout, nz, act);
    }
}

extern "C" void kernel_launch(void* const* d_in, const int* in_sizes, int n_in,
                              void* d_out, int out_size) {
    const float* x   = (const float*)d_in[0];
    const float* f1  = (const float*)d_in[1];
    const float* f2  = (const float*)d_in[2];
    const float* ff1 = (const float*)d_in[3];
    const float* ff2 = (const float*)d_in[4];
    const float* vp0w = (const float*)d_in[5];  const float* vp0b = (const float*)d_in[6];
    const float* vp1w = (const float*)d_in[7];  const float* vp1b = (const float*)d_in[8];
    const float* so0w = (const float*)d_in[9];  const float* so0b = (const float*)d_in[10];
    const float* so1w = (const float*)d_in[11]; const float* so1b = (const float*)d_in[12];
    const float* so2w = (const float*)d_in[13]; const float* so2b = (const float*)d_in[14];
    const float* so3w = (const float*)d_in[15]; const float* so3b = (const float*)d_in[16];
    const float* aw0w = (const float*)d_in[17]; const float* aw0b = (const float*)d_in[18];
    const float* aw1w = (const float*)d_in[19]; const float* aw1b = (const float*)d_in[20];
    const float* aw2w = (const float*)d_in[21]; const float* aw2b = (const float*)d_in[22];
    const float* aw3w = (const float*)d_in[23]; const float* aw3b = (const float*)d_in[24];
    const float* op0w = (const float*)d_in[25]; const float* op0b = (const float*)d_in[26];
    const float* op1w = (const float*)d_in[27]; const float* op1b = (const float*)d_in[28];

    float *extra, *b192a, *value, *b64a, *b64b, *so, *aw, *attn, *part;
    cudaGetSymbolAddress((void**)&extra, g_extra);
    cudaGetSymbolAddress((void**)&b192a, g_b192a);
    cudaGetSymbolAddress((void**)&value, g_value);
    cudaGetSymbolAddress((void**)&b64a,  g_b64a);
    cudaGetSymbolAddress((void**)&b64b,  g_b64b);
    cudaGetSymbolAddress((void**)&so,    g_so);
    cudaGetSymbolAddress((void**)&aw,    g_aw);
    cudaGetSymbolAddress((void**)&attn,  g_attn);
    cudaGetSymbolAddress((void**)&part,  g_part);

    // 1. flow composition + extra flow channels
    k_flows<<<4, 256>>>(f1, f2, ff1, ff2);
    // 2. six flow-warped frames + frame0 copy into extra
    k_warp<<<28, 256>>>(x);
    // 3. value projection (192->192 lrelu, 192->192)
    launch_conv(x,     vp0w, vp0b, b192a, nullptr, part, 192, 192, 1, 6);
    launch_conv(b192a, vp1w, vp1b, value, nullptr, part, 192, 192, 0, 6);
    k_vperm<<<(24 * HW * 8 + 255) / 256, 256>>>();
    // 4. sampling-offset head
    launch_conv(extra, so0w, so0b, b64a, nullptr, part, 460, 64,   1, 15);
    launch_conv(b64a,  so1w, so1b, b64b, nullptr, part, 64,  64,   1, 8);
    launch_conv(b64b,  so2w, so2b, b64a, nullptr, part, 64,  64,   1, 8);
    launch_conv(b64a,  so3w, so3b, so,   nullptr, part, 64,  1728, 0, 1);
    // 5. attention-weight head
    launch_conv(extra, aw0w, aw0b, b64a, nullptr, part, 460, 64,   1, 15);
    launch_conv(b64a,  aw1w, aw1b, b64b, nullptr, part, 64,  64,   1, 8);
    launch_conv(b64b,  aw2w, aw2b, b64a, nullptr, part, 64,  64,   1, 8);
    launch_conv(b64a,  aw3w, aw3b, aw,   nullptr, part, 64,  7776, 0, 1);
    // 6. softmax (compact [q][m][324])
    { dim3 g(24, 4); k_softmax<<<g, 256>>>(); }
    // 7. deformable attention sampling
    k_sample<<<3072, 256>>>();
    // 8. output projection + residual
    launch_conv(attn,  op0w, op0b, b192a,          nullptr, part, 192, 192, 1, 6);
    launch_conv(b192a, op1w, op1b, (float*)d_out,  x,       part, 192, 192, 0, 6);
}

// round 10
// speedup vs baseline: 1.1938x; 1.1137x over previous
#include <cuda_runtime.h>
#include <math.h>

// Problem constants: n=1, t=3, c=64, h=w=32
#define HW 1024

// ---------------- static scratch (no allocations allowed) ----------------
__device__ float g_extra [460 * HW];
__device__ float g_b192a [192 * HW];
__device__ float g_value [192 * HW];
__device__ float g_vperm [24 * HW * 8];     // [(m*3+l)][pix][d]
__device__ float g_b64a  [64 * HW];
__device__ float g_b64b  [64 * HW];
__device__ float g_so    [1728 * HW];
__device__ float g_aw    [7776 * HW];
__device__ float g_awsoft[7776 * HW];       // [q][m][324] compact
__device__ float g_attn  [192 * HW];
__device__ float g_part  [6 * 192 * HW];    // split-K partials, 192-ch convs
__device__ float g_part2 [15 * 64 * HW];    // split-K partials, 64-ch convs

// flow channel base in g_extra for (ti, l); -1 = zero flow
__constant__ int c_flowtbl[9] = {-1, 448, 450, 452, -1, 454, 458, 456, -1};
__constant__ int c_srcfrm[6]  = {1, 2, 0, 2, 1, 0};
__constant__ int c_flowbase[6]= {448, 450, 452, 454, 456, 458};

// ---------------- f32x2 packed-FMA helpers (sm_103a FFMA2) ----------------
__device__ __forceinline__ unsigned long long pack2(float v) {
    unsigned long long r;
    asm("mov.b64 %0, {%1, %1};" : "=l"(r) : "f"(v));
    return r;
}
__device__ __forceinline__ void ffma2(unsigned long long& d,
                                      unsigned long long a, unsigned long long b) {
    asm("fma.rn.f32x2 %0, %1, %2, %0;" : "+l"(d) : "l"(a), "l"(b));
}
__device__ __forceinline__ void unpack2(unsigned long long v, float& lo, float& hi) {
    asm("mov.b64 {%0, %1}, %2;" : "=f"(lo), "=f"(hi) : "l"(v));
}

// ---------------- flow composition ----------------
__device__ __forceinline__ void bilin2(const float* __restrict__ img, float px, float py,
                                       float& ox, float& oy) {
    float fx = floorf(px), fy = floorf(py);
    int x0 = (int)fx, y0 = (int)fy;
    float ax = px - fx, ay = py - fy;
    ox = 0.f; oy = 0.f;
    #pragma unroll
    for (int dy = 0; dy < 2; dy++)
        #pragma unroll
        for (int dx = 0; dx < 2; dx++) {
            int xi = x0 + dx, yi = y0 + dy;
            if (xi >= 0 && xi < 32 && yi >= 0 && yi < 32) {
                float w = (dx ? ax : 1.f - ax) * (dy ? ay : 1.f - ay);
                int o = yi * 32 + xi;
                ox += w * img[o];
                oy += w * img[HW + o];
            }
        }
}

__global__ void k_flows(const float* __restrict__ f1, const float* __restrict__ f2,
                        const float* __restrict__ ff1, const float* __restrict__ ff2) {
    int pix = blockIdx.x * blockDim.x + threadIdx.x;
    if (pix >= HW) return;
    int y = pix >> 5, x = pix & 31;
    float f1x = f1[pix],  f1y = f1[HW + pix];
    float ff2x = ff2[pix], ff2y = ff2[HW + pix];
    float wf2x, wf2y;   bilin2(f2,  (float)x + f1x,  (float)y + f1y,  wf2x, wf2y);
    float wff1x, wff1y; bilin2(ff1, (float)x + ff2x, (float)y + ff2y, wff1x, wff1y);
    g_extra[448*HW + pix] = f1x;            g_extra[449*HW + pix] = f1y;
    g_extra[450*HW + pix] = f1x + wf2x;     g_extra[451*HW + pix] = f1y + wf2y;
    g_extra[452*HW + pix] = ff1[pix];       g_extra[453*HW + pix] = ff1[HW + pix];
    g_extra[454*HW + pix] = f2[pix];        g_extra[455*HW + pix] = f2[HW + pix];
    g_extra[456*HW + pix] = ff2x;           g_extra[457*HW + pix] = ff2y;
    g_extra[458*HW + pix] = ff2x + wff1x;   g_extra[459*HW + pix] = ff2y + wff1y;
}

// ---------------- warp 6 frames + copy frame0 into extra ----------------
__global__ void k_warp(const float* __restrict__ x) {
    int gid = blockIdx.x * blockDim.x + threadIdx.x;   // 7 * 1024
    int j = gid >> 10, pix = gid & 1023;
    if (j >= 7) return;
    if (j == 6) {
        #pragma unroll 4
        for (int ch = 0; ch < 64; ch++)
            g_extra[ch * HW + pix] = x[ch * HW + pix];
        return;
    }
    int y = pix >> 5, xc = pix & 31;
    int fb = c_flowbase[j];
    float fx = g_extra[fb * HW + pix], fy = g_extra[(fb + 1) * HW + pix];
    float px = (float)xc + fx, py = (float)y + fy;
    float flx = floorf(px), fly = floorf(py);
    int x0 = (int)flx, y0 = (int)fly;
    float ax = px - flx, ay = py - fly;
    int   toff[4]; float tw[4];
    #pragma unroll
    for (int dy = 0; dy < 2; dy++)
        #pragma unroll
        for (int dx = 0; dx < 2; dx++) {
            int xi = x0 + dx, yi = y0 + dy, t = dy * 2 + dx;
            bool ok = (xi >= 0 && xi < 32 && yi >= 0 && yi < 32);
            toff[t] = ok ? (yi * 32 + xi) : 0;
            tw[t] = ok ? (dx ? ax : 1.f - ax) * (dy ? ay : 1.f - ay) : 0.f;
        }
    const float* src = x + c_srcfrm[j] * 64 * HW;
    int dst = 64 * (1 + j);
    for (int ch = 0; ch < 64; ch++) {
        const float* im = src + ch * HW;
        float v = tw[0]*im[toff[0]] + tw[1]*im[toff[1]] + tw[2]*im[toff[2]] + tw[3]*im[toff[3]];
        g_extra[(dst + ch) * HW + pix] = v;
    }
}

// ---------------- generic 3x3 SAME conv, implicit GEMM, FFMA2 ----------------
// tile: 64 out-ch x (4 rows x 32 cols), 256 threads, 8co x 4px per thread.
// Loaders fully unrolled with compile-time index decomposition (no divisions).
__global__ void __launch_bounds__(256)
k_conv(const float* __restrict__ in, const float* __restrict__ wt,
       const float* __restrict__ bias, float* __restrict__ out,
       const float* __restrict__ residual,
       int Cin, int Cout, int act, int nz, int total_chunks, int cpz) {
    __shared__ float si[8 * 6 * 34];                      // [ci][row(6)][col(34)]
    __shared__ __align__(16) float sw[8 * 9 * 68];        // [(ci*9+k)][co pad 68]
    int tid = threadIdx.x;
    int col = tid & 31, cogrp = tid >> 5;
    int co_base = blockIdx.x * 64;
    int r_base = blockIdx.y * 4;
    int z = blockIdx.z;
    int c0 = z * cpz;
    int c1 = min(total_chunks, c0 + cpz);

    // loader-role indices (hoisted out of the chunk loop)
    int li_a  = tid >> 5, li_c = tid & 31;        // si loader: ci, col
    int lw_co = tid >> 2, lw_b = tid & 3;         // sw loader: co, quarter
    int gco_l = co_base + lw_co;
    bool cov  = (gco_l < Cout);
    const float* wrow = wt + (size_t)gco_l * Cin * 9 + lw_b * 18;
    float* swp = &sw[(lw_b * 18) * 68 + lw_co];

    unsigned long long acc2[4][4];   // [co-pair p][row r], lo=co 2p, hi=co 2p+1
    #pragma unroll
    for (int p = 0; p < 4; p++)
        #pragma unroll
        for (int r = 0; r < 4; r++) acc2[p][r] = 0ULL;

    for (int ck = c0; ck < c1; ck++) {
        int ci0 = ck * 8;
        // ---- input tile with halo, no divisions: thread = (ci, col) ----
        {
            int gci = ci0 + li_a;
            bool civ = (gci < Cin);
            const float* ib = in + (size_t)gci * HW + (r_base - 1) * 32;
            float* sip = &si[li_a * 204];
            #pragma unroll
            for (int rr = 0; rr < 6; rr++) {
                int gy = r_base - 1 + rr;
                bool rv = civ && (gy >= 0) && (gy < 32);
                sip[rr * 34 + li_c] = (rv && li_c >= 1) ? ib[rr * 32 + li_c - 1] : 0.f;
                if (li_c < 2)
                    sip[rr * 34 + 32 + li_c] = (rv && li_c == 0) ? ib[rr * 32 + 31] : 0.f;
            }
        }
        // ---- weights: 18 consecutive floats per thread, all indices affine ----
        {
            const float* wp = wrow + ci0 * 9;
            int ci_lo = ci0 + lw_b * 2;
            bool cv0 = cov && (ci_lo < Cin);
            bool cv1 = cov && (ci_lo + 1 < Cin);
            #pragma unroll
            for (int it = 0; it < 18; it++) {
                bool v = (it < 9) ? cv0 : cv1;
                swp[it * 68] = v ? wp[it] : 0.f;
            }
        }
        __syncthreads();
        for (int ci = 0; ci < 8; ci++) {
            float iv[6][3];
            #pragma unroll
            for (int rr = 0; rr < 6; rr++)
                #pragma unroll
                for (int cc = 0; cc < 3; cc++)
                    iv[rr][cc] = si[(ci * 6 + rr) * 34 + col + cc];
            #pragma unroll
            for (int ky = 0; ky < 3; ky++)
                #pragma unroll
                for (int kx = 0; kx < 3; kx++) {
                    // 8 weights for this (ci,k): 2x LDS.128 -> 4 f32x2 pairs (warp-uniform)
                    const float* wq = &sw[(ci * 9 + ky * 3 + kx) * 68 + cogrp * 8];
                    ulonglong2 wA = *(const ulonglong2*)wq;        // pairs (0,1),(2,3)
                    ulonglong2 wB = *(const ulonglong2*)(wq + 4);  // pairs (4,5),(6,7)
                    #pragma unroll
                    for (int r = 0; r < 4; r++) {
                        unsigned long long ivv = pack2(iv[r + ky][kx]);
                        ffma2(acc2[0][r], wA.x, ivv);
                        ffma2(acc2[1][r], wA.y, ivv);
                        ffma2(acc2[2][r], wB.x, ivv);
                        ffma2(acc2[3][r], wB.y, ivv);
                    }
                }
        }
        __syncthreads();
    }

    if (nz == 1) {
        #pragma unroll
        for (int p = 0; p < 4; p++) {
            int co0 = co_base + cogrp * 8 + p * 2;   // Cout always even -> pair never straddles
            if (co0 < Cout) {
                float b0 = bias[co0], b1 = bias[co0 + 1];
                #pragma unroll
                for (int r = 0; r < 4; r++) {
                    float lo, hi; unpack2(acc2[p][r], lo, hi);
                    int oi = co0 * HW + (r_base + r) * 32 + col;
                    float v0 = lo + b0, v1 = hi + b1;
                    if (act) { v0 = (v0 >= 0.f) ? v0 : 0.1f * v0;
                               v1 = (v1 >= 0.f) ? v1 : 0.1f * v1; }
                    if (residual) { v0 += residual[oi]; v1 += residual[oi + HW]; }
                    out[oi] = v0;
                    out[oi + HW] = v1;
                }
            }
        }
    } else {
        float* po = out + (size_t)z * Cout * HW;
        #pragma unroll
        for (int p = 0; p < 4; p++) {
            int co0 = co_base + cogrp * 8 + p * 2;
            if (co0 < Cout)
                #pragma unroll
                for (int r = 0; r < 4; r++) {
                    float lo, hi; unpack2(acc2[p][r], lo, hi);
                    int oi = co0 * HW + (r_base + r) * 32 + col;
                    po[oi] = lo;
                    po[oi + HW] = hi;
                }
        }
    }
}

// ---------------- split-K reduce, float4 vectorized ----------------
__global__ void k_finalize(const float* __restrict__ part, const float* __restrict__ bias,
                           float* __restrict__ out, const float* __restrict__ residual,
                           int Cout, int nz, int act) {
    int i4 = blockIdx.x * blockDim.x + threadIdx.x;
    int n4 = (Cout * HW) >> 2;
    if (i4 >= n4) return;
    int ch = i4 >> 8;                      // (i4*4)>>10
    float4 v = make_float4(0.f, 0.f, 0.f, 0.f);
    for (int z = 0; z < nz; z++) {
        float4 p = ((const float4*)(part + (size_t)z * Cout * HW))[i4];
        v.x += p.x; v.y += p.y; v.z += p.z; v.w += p.w;
    }
    float b = bias[ch];
    v.x += b; v.y += b; v.z += b; v.w += b;
    if (act) {
        v.x = (v.x >= 0.f) ? v.x : 0.1f * v.x;
        v.y = (v.y >= 0.f) ? v.y : 0.1f * v.y;
        v.z = (v.z >= 0.f) ? v.z : 0.1f * v.z;
        v.w = (v.w >= 0.f) ? v.w : 0.1f * v.w;
    }
    if (residual) {
        float4 r = ((const float4*)residual)[i4];
        v.x += r.x; v.y += r.y; v.z += r.z; v.w += r.w;
    }
    ((float4*)out)[i4] = v;
}

// ---------------- value permute: [l*64+m*8+d][pix] -> [(m*3+l)][pix][d] ----------------
__global__ void k_vperm() {
    int idx = blockIdx.x * blockDim.x + threadIdx.x;   // 24*1024*8
    if (idx >= 24 * HW * 8) return;
    int ml = idx >> 13; int rem = idx & 8191;
    int pix = rem >> 3; int d = rem & 7;
    int m = ml / 3, l = ml - m * 3;
    g_vperm[idx] = g_value[(l * 64 + m * 8 + d) * HW + pix];
}

// ---------------- softmax over 324 per (q, m), compact output ----------------
__global__ void k_softmax() {
    int b = blockIdx.x;                 // 24 = ti*8+m
    int ti = b >> 3, m = b & 7;
    int p = blockIdx.y * blockDim.x + threadIdx.x;   // gridDim.y = 4
    if (p >= HW) return;
    int chbase = ti * 2592 + m * 324;
    float mx = -1e30f, sm = 0.f;
    for (int j = 0; j < 324; j++) {
        float v = g_aw[(chbase + j) * HW + p];
        float nm = fmaxf(mx, v);
        sm = sm * __expf(mx - nm) + __expf(v - nm);
        mx = nm;
    }
    float inv = 1.f / sm;
    int ob = ((ti * HW + p) * 8 + m) * 324;
    for (int j = 0; j < 324; j++) {
        float v = g_aw[(chbase + j) * HW + p];
        g_awsoft[ob + j] = __expf(v - mx) * inv;
    }
}

// ---------------- deformable attention sampling: one warp per (q, m) ----------------
__global__ void __launch_bounds__(256) k_sample() {
    int q = blockIdx.x;                 // 3072
    int m = threadIdx.x >> 5;
    int lane = threadIdx.x & 31;
    int ti = q >> 10, pix = q & 1023;
    int y = pix >> 5, x = pix & 31;

    float acc[8];
    #pragma unroll
    for (int d = 0; d < 8; d++) acc[d] = 0.f;

    for (int s = lane; s < 324; s += 32) {
        int l = s / 108; int rem = s - l * 108;
        int p = rem / 9;  int k = rem - p * 9;
        int soch = ((ti * 8 + m) * 3 + l) * 24 + p * 2;
        float ox = g_so[soch * HW + pix];
        float oy = g_so[(soch + 1) * HW + pix];
        int fb = c_flowtbl[ti * 3 + l];
        if (fb >= 0) {
            ox += g_extra[fb * HW + pix];
            oy += g_extra[(fb + 1) * HW + pix];
        }
        float px = (float)x + ox + (float)(k / 3 - 1);
        float py = (float)y + oy + (float)(k % 3 - 1);
        float aw = g_awsoft[(q * 8 + m) * 324 + s];
        float flx = floorf(px), fly = floorf(py);
        int x0 = (int)flx, y0 = (int)fly;
        float ax = px - flx, ay = py - fly;
        const float* vb = g_vperm + (m * 3 + l) * (HW * 8);
        #pragma unroll
        for (int dy = 0; dy < 2; dy++)
            #pragma unroll
            for (int dx = 0; dx < 2; dx++) {
                int xi = x0 + dx, yi = y0 + dy;
                if (xi >= 0 && xi < 32 && yi >= 0 && yi < 32) {
                    float wgt = aw * (dx ? ax : 1.f - ax) * (dy ? ay : 1.f - ay);
                    const float4* vp = (const float4*)(vb + (yi * 32 + xi) * 8);
                    float4 a = vp[0], bb = vp[1];
                    acc[0] += wgt * a.x;  acc[1] += wgt * a.y;
                    acc[2] += wgt * a.z;  acc[3] += wgt * a.w;
                    acc[4] += wgt * bb.x; acc[5] += wgt * bb.y;
                    acc[6] += wgt * bb.z; acc[7] += wgt * bb.w;
                }
            }
    }
    #pragma unroll
    for (int d = 0; d < 8; d++)
        #pragma unroll
        for (int off = 16; off > 0; off >>= 1)
            acc[d] += __shfl_xor_sync(0xffffffffu, acc[d], off);
    if (lane == 0) {
        int ob = (ti * 64 + m * 8) * HW + pix;
        #pragma unroll
        for (int d = 0; d < 8; d++) g_attn[ob + d * HW] = acc[d];
    }
}

// ---------------- host side ----------------
static void conv_main(const float* in, const float* wt, const float* bs,
                      float* out, const float* res, float* part,
                      int Cin, int Cout, int act, int nz) {
    int chunks = (Cin + 7) / 8;
    int cpz = (chunks + nz - 1) / nz;
    dim3 grid((Cout + 63) / 64, 8, nz);
    if (nz == 1)
        k_conv<<<grid, 256>>>(in, wt, bs, out, res, Cin, Cout, act, 1, chunks, cpz);
    else
        k_conv<<<grid, 256>>>(in, wt, nullptr, part, nullptr, Cin, Cout, 0, nz, chunks, cpz);
}
static void conv_fin(const float* bs, float* out, const float* res, float* part,
                     int Cout, int act, int nz) {
    if (nz > 1)
        k_finalize<<<(Cout * HW / 4 + 255) / 256, 256>>>(part, bs, out, res, Cout, nz, act);
}

extern "C" void kernel_launch(void* const* d_in, const int* in_sizes, int n_in,
                              void* d_out, int out_size) {
    const float* x   = (const float*)d_in[0];
    const float* f1  = (const float*)d_in[1];
    const float* f2  = (const float*)d_in[2];
    const float* ff1 = (const float*)d_in[3];
    const float* ff2 = (const float*)d_in[4];
    const float* vp0w = (const float*)d_in[5];  const float* vp0b = (const float*)d_in[6];
    const float* vp1w = (const float*)d_in[7];  const float* vp1b = (const float*)d_in[8];
    const float* so0w = (const float*)d_in[9];  const float* so0b = (const float*)d_in[10];
    const float* so1w = (const float*)d_in[11]; const float* so1b = (const float*)d_in[12];
    const float* so2w = (const float*)d_in[13]; const float* so2b = (const float*)d_in[14];
    const float* so3w = (const float*)d_in[15]; const float* so3b = (const float*)d_in[16];
    const float* aw0w = (const float*)d_in[17]; const float* aw0b = (const float*)d_in[18];
    const float* aw1w = (const float*)d_in[19]; const float* aw1b = (const float*)d_in[20];
    const float* aw2w = (const float*)d_in[21]; const float* aw2b = (const float*)d_in[22];
    const float* aw3w = (const float*)d_in[23]; const float* aw3b = (const float*)d_in[24];
    const float* op0w = (const float*)d_in[25]; const float* op0b = (const float*)d_in[26];
    const float* op1w = (const float*)d_in[27]; const float* op1b = (const float*)d_in[28];

    float *extra, *b192a, *value, *b64a, *b64b, *so, *aw, *attn, *part, *part2;
    cudaGetSymbolAddress((void**)&extra, g_extra);
    cudaGetSymbolAddress((void**)&b192a, g_b192a);
    cudaGetSymbolAddress((void**)&value, g_value);
    cudaGetSymbolAddress((void**)&b64a,  g_b64a);
    cudaGetSymbolAddress((void**)&b64b,  g_b64b);
    cudaGetSymbolAddress((void**)&so,    g_so);
    cudaGetSymbolAddress((void**)&aw,    g_aw);
    cudaGetSymbolAddress((void**)&attn,  g_attn);
    cudaGetSymbolAddress((void**)&part,  g_part);
    cudaGetSymbolAddress((void**)&part2, g_part2);

    // launch order arranged so ncu's "-s 5 -c 1" (6th launch) captures a k_conv.
    // 192-ch convs use g_part; 64-ch convs use g_part2 -> interleaving is race-free.
    k_flows<<<4, 256>>>(f1, f2, ff1, ff2);                               // 1
    k_warp<<<28, 256>>>(x);                                              // 2
    conv_main(extra, so0w, so0b, b64a, nullptr, part2, 460, 64, 1, 15);  // 3
    conv_fin(so0b, b64a, nullptr, part2, 64, 1, 15);                     // 4
    conv_main(x, vp0w, vp0b, b192a, nullptr, part, 192, 192, 1, 6);      // 5  -> part
    conv_main(b64a, so1w, so1b, b64b, nullptr, part2, 64, 64, 1, 8);     // 6  -> part2 (ncu capture)
    conv_fin(vp0b, b192a, nullptr, part, 192, 1, 6);                     // 7  reads part
    conv_fin(so1b, b64b, nullptr, part2, 64, 1, 8);                      // 8  reads part2
    conv_main(b192a, vp1w, vp1b, value, nullptr, part, 192, 192, 0, 6);  // 9  -> part
    conv_main(b64b, so2w, so2b, b64a, nullptr, part2, 64, 64, 1, 8);     // 10 -> part2
    conv_fin(vp1b, value, nullptr, part, 192, 0, 6);                     // 11 reads part
    conv_fin(so2b, b64a, nullptr, part2, 64, 1, 8);                      // 12 reads part2
    k_vperm<<<(24 * HW * 8 + 255) / 256, 256>>>();                       // 13
    conv_main(b64a, so3w, so3b, so, nullptr, part2, 64, 1728, 0, 1);     // 14 (nz=1, direct)
    // attention-weight head (strictly sequential main->fin on part2)
    conv_main(extra, aw0w, aw0b, b64a, nullptr, part2, 460, 64, 1, 15);
    conv_fin(aw0b, b64a, nullptr, part2, 64, 1, 15);
    conv_main(b64a, aw1w, aw1b, b64b, nullptr, part2, 64, 64, 1, 8);
    conv_fin(aw1b, b64b, nullptr, part2, 64, 1, 8);
    conv_main(b64b, aw2w, aw2b, b64a, nullptr, part2, 64, 64, 1, 8);
    conv_fin(aw2b, b64a, nullptr, part2, 64, 1, 8);
    conv_main(b64a, aw3w, aw3b, aw, nullptr, part2, 64, 7776, 0, 1);
    // softmax (compact [q][m][324])
    { dim3 g(24, 4); k_softmax<<<g, 256>>>(); }
    // deformable attention sampling
    k_sample<<<3072, 256>>>();
    // output projection + residual (sequential on part)
    conv_main(attn, op0w, op0b, b192a, nullptr, part, 192, 192, 1, 6);
    conv_fin(op0b, b192a, nullptr, part, 192, 1, 6);
    conv_main(b192a, op1w, op1b, (float*)d_out, x, part, 192, 192, 0, 6);
    conv_fin(op1b, (float*)d_out, x, part, 192, 0, 6);
}

// round 13
// speedup vs baseline: 1.5957x; 1.3366x over previous
#include <cuda_runtime.h>
#include <math.h>

// Problem constants: n=1, t=3, c=64, h=w=32
#define HW 1024

// ---------------- static scratch (no allocations allowed) ----------------
__device__ float g_extra [460 * HW];
__device__ float g_b192a [192 * HW];
__device__ float g_value [192 * HW];
__device__ float g_vperm [24 * HW * 8];     // [(m*3+l)][pix][d]
__device__ float g_b64a  [64 * HW];         // so-chain buffers
__device__ float g_b64b  [64 * HW];
__device__ float g_b64c  [64 * HW];         // aw-chain buffers
__device__ float g_b64d  [64 * HW];
__device__ float g_so    [1728 * HW];
__device__ float g_aw    [7776 * HW];
__device__ float g_attn  [192 * HW];
__device__ float g_part  [12 * 192 * HW];   // split-K partials, 192-ch convs
__device__ float g_part2 [15 * 64 * HW];    // split-K partials, job-A 64-ch convs
__device__ float g_part3 [15 * 64 * HW];    // split-K partials, job-B 64-ch convs

// flow channel base in g_extra for (ti, l); -1 = zero flow
__constant__ int c_flowtbl[9] = {-1, 448, 450, 452, -1, 454, 458, 456, -1};
__constant__ int c_srcfrm[6]  = {1, 2, 0, 2, 1, 0};
__constant__ int c_flowbase[6]= {448, 450, 452, 454, 456, 458};

// ---------------- f32x2 packed-FMA helpers (sm_103a FFMA2) ----------------
__device__ __forceinline__ unsigned long long pack2(float v) {
    unsigned long long r;
    asm("mov.b64 %0, {%1, %1};" : "=l"(r) : "f"(v));
    return r;
}
__device__ __forceinline__ void ffma2(unsigned long long& d,
                                      unsigned long long a, unsigned long long b) {
    asm("fma.rn.f32x2 %0, %1, %2, %0;" : "+l"(d) : "l"(a), "l"(b));
}
__device__ __forceinline__ void unpack2(unsigned long long v, float& lo, float& hi) {
    asm("mov.b64 {%0, %1}, %2;" : "=f"(lo), "=f"(hi) : "l"(v));
}

// ---------------- flow composition ----------------
__device__ __forceinline__ void bilin2(const float* __restrict__ img, float px, float py,
                                       float& ox, float& oy) {
    float fx = floorf(px), fy = floorf(py);
    int x0 = (int)fx, y0 = (int)fy;
    float ax = px - fx, ay = py - fy;
    ox = 0.f; oy = 0.f;
    #pragma unroll
    for (int dy = 0; dy < 2; dy++)
        #pragma unroll
        for (int dx = 0; dx < 2; dx++) {
            int xi = x0 + dx, yi = y0 + dy;
            if (xi >= 0 && xi < 32 && yi >= 0 && yi < 32) {
                float w = (dx ? ax : 1.f - ax) * (dy ? ay : 1.f - ay);
                int o = yi * 32 + xi;
                ox += w * img[o];
                oy += w * img[HW + o];
            }
        }
}

__global__ void k_flows(const float* __restrict__ f1, const float* __restrict__ f2,
                        const float* __restrict__ ff1, const float* __restrict__ ff2) {
    int pix = blockIdx.x * blockDim.x + threadIdx.x;
    if (pix >= HW) return;
    int y = pix >> 5, x = pix & 31;
    float f1x = f1[pix],  f1y = f1[HW + pix];
    float ff2x = ff2[pix], ff2y = ff2[HW + pix];
    float wf2x, wf2y;   bilin2(f2,  (float)x + f1x,  (float)y + f1y,  wf2x, wf2y);
    float wff1x, wff1y; bilin2(ff1, (float)x + ff2x, (float)y + ff2y, wff1x, wff1y);
    g_extra[448*HW + pix] = f1x;            g_extra[449*HW + pix] = f1y;
    g_extra[450*HW + pix] = f1x + wf2x;     g_extra[451*HW + pix] = f1y + wf2y;
    g_extra[452*HW + pix] = ff1[pix];       g_extra[453*HW + pix] = ff1[HW + pix];
    g_extra[454*HW + pix] = f2[pix];        g_extra[455*HW + pix] = f2[HW + pix];
    g_extra[456*HW + pix] = ff2x;           g_extra[457*HW + pix] = ff2y;
    g_extra[458*HW + pix] = ff2x + wff1x;   g_extra[459*HW + pix] = ff2y + wff1y;
}

// ---------------- warp 6 frames + copy frame0 into extra (8 ch/thread) ----------------
__global__ void k_warp(const float* __restrict__ x) {
    int gid = blockIdx.x * blockDim.x + threadIdx.x;   // 7 * 8 * 1024
    if (gid >= 7 * 8 * 1024) return;
    int j = gid >> 13;                 // 0..6
    int rem = gid & 8191;
    int cg = rem >> 10;                // channel group 0..7
    int pix = rem & 1023;
    int ch0 = cg * 8;
    if (j == 6) {
        #pragma unroll
        for (int c = 0; c < 8; c++)
            g_extra[(ch0 + c) * HW + pix] = x[(ch0 + c) * HW + pix];
        return;
    }
    int y = pix >> 5, xc = pix & 31;
    int fb = c_flowbase[j];
    float fx = g_extra[fb * HW + pix], fy = g_extra[(fb + 1) * HW + pix];
    float px = (float)xc + fx, py = (float)y + fy;
    float flx = floorf(px), fly = floorf(py);
    int x0 = (int)flx, y0 = (int)fly;
    float ax = px - flx, ay = py - fly;
    int   toff[4]; float tw[4];
    #pragma unroll
    for (int dy = 0; dy < 2; dy++)
        #pragma unroll
        for (int dx = 0; dx < 2; dx++) {
            int xi = x0 + dx, yi = y0 + dy, t = dy * 2 + dx;
            bool ok = (xi >= 0 && xi < 32 && yi >= 0 && yi < 32);
            toff[t] = ok ? (yi * 32 + xi) : 0;
            tw[t] = ok ? (dx ? ax : 1.f - ax) * (dy ? ay : 1.f - ay) : 0.f;
        }
    const float* src = x + c_srcfrm[j] * 64 * HW + ch0 * HW;
    int dst = 64 * (1 + j) + ch0;
    #pragma unroll
    for (int c = 0; c < 8; c++) {
        const float* im = src + c * HW;
        float v = tw[0]*im[toff[0]] + tw[1]*im[toff[1]] + tw[2]*im[toff[2]] + tw[3]*im[toff[3]];
        g_extra[(dst + c) * HW + pix] = v;
    }
}

// ---------------- 3x3 SAME conv, implicit GEMM, FFMA2, dual-job ----------------
// tile: 64 out-ch x (4 rows x 32 cols), 256 threads, 8co x 4px per thread.
// Optional second job (in2 != null): blocks with blockIdx.x >= nx1 run job B.
// Jobs must share Cin / nz / chunks / cpz / act.
__global__ void __launch_bounds__(256)
k_conv(const float* in, const float* wt, const float* bias, float* out,
       const float* residual,
       const float* in2, const float* wt2, const float* bias2, float* out2,
       int nx1, int Cout2,
       int Cin, int Cout, int act, int nz, int total_chunks, int cpz) {
    __shared__ float si[8 * 6 * 34];                      // [ci][row(6)][col(34)]
    __shared__ __align__(16) float sw[8 * 9 * 68];        // [(ci*9+k)][co pad 68]
    int tid = threadIdx.x;
    int col = tid & 31, cogrp = tid >> 5;
    int bx = blockIdx.x;
    if (in2 && bx >= nx1) {
        bx -= nx1;
        in = in2; wt = wt2; bias = bias2; out = out2; Cout = Cout2;
    }
    int co_base = bx * 64;
    int r_base = blockIdx.y * 4;
    int z = blockIdx.z;
    int c0 = z * cpz;
    int c1 = min(total_chunks, c0 + cpz);

    // loader-role indices (hoisted out of the chunk loop)
    int li_a  = tid >> 5, li_c = tid & 31;        // si loader: ci, col
    int lw_co = tid >> 2, lw_b = tid & 3;         // sw loader: co, quarter
    int gco_l = co_base + lw_co;
    bool cov  = (gco_l < Cout);
    const float* wrow = wt + (size_t)(cov ? gco_l : 0) * Cin * 9 + lw_b * 18;
    float* swp = &sw[(lw_b * 18) * 68 + lw_co];

    unsigned long long acc2[4][4];   // [co-pair p][row r], lo=co 2p, hi=co 2p+1
    #pragma unroll
    for (int p = 0; p < 4; p++)
        #pragma unroll
        for (int r = 0; r < 4; r++) acc2[p][r] = 0ULL;

    for (int ck = c0; ck < c1; ck++) {
        int ci0 = ck * 8;
        // ---- input tile with halo, no divisions: thread = (ci, col) ----
        {
            int gci = ci0 + li_a;
            bool civ = (gci < Cin);
            const float* ib = in + (size_t)(civ ? gci : 0) * HW + (r_base - 1) * 32;
            float* sip = &si[li_a * 204];
            #pragma unroll
            for (int rr = 0; rr < 6; rr++) {
                int gy = r_base - 1 + rr;
                bool rv = civ && (gy >= 0) && (gy < 32);
                sip[rr * 34 + li_c] = (rv && li_c >= 1) ? ib[rr * 32 + li_c - 1] : 0.f;
                if (li_c < 2)
                    sip[rr * 34 + 32 + li_c] = (rv && li_c == 0) ? ib[rr * 32 + 31] : 0.f;
            }
        }
        // ---- weights: 18 consecutive floats per thread, all indices affine ----
        {
            const float* wp = wrow + ci0 * 9;
            int ci_lo = ci0 + lw_b * 2;
            bool cv0 = cov && (ci_lo < Cin);
            bool cv1 = cov && (ci_lo + 1 < Cin);
            #pragma unroll
            for (int it = 0; it < 18; it++) {
                bool v = (it < 9) ? cv0 : cv1;
                swp[it * 68] = v ? wp[it] : 0.f;
            }
        }
        __syncthreads();
        for (int ci = 0; ci < 8; ci++) {
            float iv[6][3];
            #pragma unroll
            for (int rr = 0; rr < 6; rr++)
                #pragma unroll
                for (int cc = 0; cc < 3; cc++)
                    iv[rr][cc] = si[(ci * 6 + rr) * 34 + col + cc];
            #pragma unroll
            for (int ky = 0; ky < 3; ky++)
                #pragma unroll
                for (int kx = 0; kx < 3; kx++) {
                    // 8 weights for this (ci,k): 2x LDS.128 -> 4 f32x2 pairs (warp-uniform)
                    const float* wq = &sw[(ci * 9 + ky * 3 + kx) * 68 + cogrp * 8];
                    ulonglong2 wA = *(const ulonglong2*)wq;        // pairs (0,1),(2,3)
                    ulonglong2 wB = *(const ulonglong2*)(wq + 4);  // pairs (4,5),(6,7)
                    #pragma unroll
                    for (int r = 0; r < 4; r++) {
                        unsigned long long ivv = pack2(iv[r + ky][kx]);
                        ffma2(acc2[0][r], wA.x, ivv);
                        ffma2(acc2[1][r], wA.y, ivv);
                        ffma2(acc2[2][r], wB.x, ivv);
                        ffma2(acc2[3][r], wB.y, ivv);
                    }
                }
        }
        __syncthreads();
    }

    if (nz == 1) {
        #pragma unroll
        for (int p = 0; p < 4; p++) {
            int co0 = co_base + cogrp * 8 + p * 2;   // Cout always even -> pair never straddles
            if (co0 < Cout) {
                float b0 = bias[co0], b1 = bias[co0 + 1];
                #pragma unroll
                for (int r = 0; r < 4; r++) {
                    float lo, hi; unpack2(acc2[p][r], lo, hi);
                    int oi = co0 * HW + (r_base + r) * 32 + col;
                    float v0 = lo + b0, v1 = hi + b1;
                    if (act) { v0 = (v0 >= 0.f) ? v0 : 0.1f * v0;
                               v1 = (v1 >= 0.f) ? v1 : 0.1f * v1; }
                    if (residual) { v0 += residual[oi]; v1 += residual[oi + HW]; }
                    out[oi] = v0;
                    out[oi + HW] = v1;
                }
            }
        }
    } else {
        float* po = out + (size_t)z * Cout * HW;
        #pragma unroll
        for (int p = 0; p < 4; p++) {
            int co0 = co_base + cogrp * 8 + p * 2;
            if (co0 < Cout)
                #pragma unroll
                for (int r = 0; r < 4; r++) {
                    float lo, hi; unpack2(acc2[p][r], lo, hi);
                    int oi = co0 * HW + (r_base + r) * 32 + col;
                    po[oi] = lo;
                    po[oi + HW] = hi;
                }
        }
    }
}

// ---------------- split-K reduce, float4, 128 threads, optional dual ----------------
__global__ void k_finalize(const float* part, const float* bias,
                           float* out, const float* res,
                           int Cout, int nz, int act,
                           const float* part2, const float* bias2, float* out2) {
    int i4 = blockIdx.x * blockDim.x + threadIdx.x;
    int n4 = (Cout * HW) >> 2;
    if (part2 && i4 >= n4) { i4 -= n4; part = part2; bias = bias2; out = out2; }
    if (i4 >= n4) return;
    int ch = i4 >> 8;                      // (i4*4)>>10
    float4 v = make_float4(0.f, 0.f, 0.f, 0.f);
    for (int z = 0; z < nz; z++) {
        float4 p = ((const float4*)(part + (size_t)z * Cout * HW))[i4];
        v.x += p.x; v.y += p.y; v.z += p.z; v.w += p.w;
    }
    float b = bias[ch];
    v.x += b; v.y += b; v.z += b; v.w += b;
    if (act) {
        v.x = (v.x >= 0.f) ? v.x : 0.1f * v.x;
        v.y = (v.y >= 0.f) ? v.y : 0.1f * v.y;
        v.z = (v.z >= 0.f) ? v.z : 0.1f * v.z;
        v.w = (v.w >= 0.f) ? v.w : 0.1f * v.w;
    }
    if (res) {
        float4 r = ((const float4*)res)[i4];
        v.x += r.x; v.y += r.y; v.z += r.z; v.w += r.w;
    }
    ((float4*)out)[i4] = v;
}

// ---------------- value permute: [l*64+m*8+d][pix] -> [(m*3+l)][pix][d] ----------------
__global__ void k_vperm() {
    int idx = blockIdx.x * blockDim.x + threadIdx.x;   // 24*1024*8
    if (idx >= 24 * HW * 8) return;
    int ml = idx >> 13; int rem = idx & 8191;
    int pix = rem >> 3; int d = rem & 7;
    int m = ml / 3, l = ml - m * 3;
    g_vperm[idx] = g_value[(l * 64 + m * 8 + d) * HW + pix];
}

// ---------------- deformable attention with fused softmax ----------------
// one warp per (q, m): load 324 logits to regs, warp softmax, sample, reduce.
__global__ void __launch_bounds__(256) k_sample() {
    int q = blockIdx.x;                 // 3072
    int m = threadIdx.x >> 5;
    int lane = threadIdx.x & 31;
    int ti = q >> 10, pix = q & 1023;
    int y = pix >> 5, x = pix & 31;
    int tm = ti * 8 + m;

    // pass 1: logits -> registers, running max
    float va[11];
    float mx = -1e30f;
    #pragma unroll
    for (int k = 0; k < 11; k++) {
        int s = lane + k * 32;
        float v = (s < 324) ? g_aw[(tm * 324 + s) * HW + pix] : -1e30f;
        va[k] = v;
        mx = fmaxf(mx, v);
    }
    #pragma unroll
    for (int off = 16; off > 0; off >>= 1)
        mx = fmaxf(mx, __shfl_xor_sync(0xffffffffu, mx, off));
    float sm = 0.f;
    #pragma unroll
    for (int k = 0; k < 11; k++) {
        int s = lane + k * 32;
        if (s < 324) sm += __expf(va[k] - mx);
    }
    #pragma unroll
    for (int off = 16; off > 0; off >>= 1)
        sm += __shfl_xor_sync(0xffffffffu, sm, off);
    float inv = 1.f / sm;

    float acc[8];
    #pragma unroll
    for (int d = 0; d < 8; d++) acc[d] = 0.f;

    #pragma unroll
    for (int k = 0; k < 11; k++) {
        int s = lane + k * 32;
        if (s >= 324) continue;
        float aw = __expf(va[k] - mx) * inv;
        int l = s / 108; int rem = s - l * 108;
        int p = rem / 9;  int kk = rem - p * 9;
        int soch = ((ti * 8 + m) * 3 + l) * 24 + p * 2;
        float ox = g_so[soch * HW + pix];
        float oy = g_so[(soch + 1) * HW + pix];
        int fb = c_flowtbl[ti * 3 + l];
        if (fb >= 0) {
            ox += g_extra[fb * HW + pix];
            oy += g_extra[(fb + 1) * HW + pix];
        }
        float px = (float)x + ox + (float)(kk / 3 - 1);
        float py = (float)y + oy + (float)(kk % 3 - 1);
        float flx = floorf(px), fly = floorf(py);
        int x0 = (int)flx, y0 = (int)fly;
        float ax = px - flx, ay = py - fly;
        const float* vb = g_vperm + (m * 3 + l) * (HW * 8);
        #pragma unroll
        for (int dy = 0; dy < 2; dy++)
            #pragma unroll
            for (int dx = 0; dx < 2; dx++) {
                int xi = x0 + dx, yi = y0 + dy;
                if (xi >= 0 && xi < 32 && yi >= 0 && yi < 32) {
                    float wgt = aw * (dx ? ax : 1.f - ax) * (dy ? ay : 1.f - ay);
                    const float4* vp = (const float4*)(vb + (yi * 32 + xi) * 8);
                    float4 a = vp[0], bb = vp[1];
                    acc[0] += wgt * a.x;  acc[1] += wgt * a.y;
                    acc[2] += wgt * a.z;  acc[3] += wgt * a.w;
                    acc[4] += wgt * bb.x; acc[5] += wgt * bb.y;
                    acc[6] += wgt * bb.z; acc[7] += wgt * bb.w;
                }
            }
    }
    #pragma unroll
    for (int d = 0; d < 8; d++)
        #pragma unroll
        for (int off = 16; off > 0; off >>= 1)
            acc[d] += __shfl_xor_sync(0xffffffffu, acc[d], off);
    if (lane == 0) {
        int ob = (ti * 64 + m * 8) * HW + pix;
        #pragma unroll
        for (int d = 0; d < 8; d++) g_attn[ob + d * HW] = acc[d];
    }
}

// ---------------- host side ----------------
static void conv_single(const float* in, const float* wt, const float* bs,
                        float* out, const float* res, float* part,
                        int Cin, int Cout, int act, int nz) {
    int chunks = (Cin + 7) / 8;
    int cpz = (chunks + nz - 1) / nz;
    dim3 grid((Cout + 63) / 64, 8, nz);
    if (nz == 1)
        k_conv<<<grid, 256>>>(in, wt, bs, out, res,
                              nullptr, nullptr, nullptr, nullptr, 0, 0,
                              Cin, Cout, act, 1, chunks, cpz);
    else
        k_conv<<<grid, 256>>>(in, wt, nullptr, part, nullptr,
                              nullptr, nullptr, nullptr, nullptr, 0, 0,
                              Cin, Cout, 0, nz, chunks, cpz);
}
// dual conv: jobs share Cin/nz/act. nz>1 -> outputs go to partA/partB.
static void conv_dual(const float* inA, const float* wtA, const float* bsA, float* outA,
                      const float* inB, const float* wtB, const float* bsB, float* outB,
                      int Cin, int CoutA, int CoutB, int act, int nz,
                      float* partA, float* partB) {
    int chunks = (Cin + 7) / 8;
    int cpz = (chunks + nz - 1) / nz;
    int nxA = (CoutA + 63) / 64, nxB = (CoutB + 63) / 64;
    dim3 grid(nxA + nxB, 8, nz);
    if (nz == 1)
        k_conv<<<grid, 256>>>(inA, wtA, bsA, outA, nullptr,
                              inB, wtB, bsB, outB, nxA, CoutB,
                              Cin, CoutA, act, 1, chunks, cpz);
    else
        k_conv<<<grid, 256>>>(inA, wtA, nullptr, partA, nullptr,
                              inB, wtB, nullptr, partB, nxA, CoutB,
                              Cin, CoutA, 0, nz, chunks, cpz);
}
static void fin_single(const float* part, const float* bs, float* out, const float* res,
                       int Cout, int act, int nz) {
    int n4 = Cout * HW / 4;
    k_finalize<<<(n4 + 127) / 128, 128>>>(part, bs, out, res, Cout, nz, act,
                                          nullptr, nullptr, nullptr);
}
static void fin_dual(const float* partA, const float* bsA, float* outA,
                     const float* partB, const float* bsB, float* outB,
                     int Cout, int act, int nz) {
    int n4 = Cout * HW / 4;
    k_finalize<<<(2 * n4 + 127) / 128, 128>>>(partA, bsA, outA, nullptr, Cout, nz, act,
                                              partB, bsB, outB);
}

extern "C" void kernel_launch(void* const* d_in, const int* in_sizes, int n_in,
                              void* d_out, int out_size) {
    const float* x   = (const float*)d_in[0];
    const float* f1  = (const float*)d_in[1];
    const float* f2  = (const float*)d_in[2];
    const float* ff1 = (const float*)d_in[3];
    const float* ff2 = (const float*)d_in[4];
    const float* vp0w = (const float*)d_in[5];  const float* vp0b = (const float*)d_in[6];
    const float* vp1w = (const float*)d_in[7];  const float* vp1b = (const float*)d_in[8];
    const float* so0w = (const float*)d_in[9];  const float* so0b = (const float*)d_in[10];
    const float* so1w = (const float*)d_in[11]; const float* so1b = (const float*)d_in[12];
    const float* so2w = (const float*)d_in[13]; const float* so2b = (const float*)d_in[14];
    const float* so3w = (const float*)d_in[15]; const float* so3b = (const float*)d_in[16];
    const float* aw0w = (const float*)d_in[17]; const float* aw0b = (const float*)d_in[18];
    const float* aw1w = (const float*)d_in[19]; const float* aw1b = (const float*)d_in[20];
    const float* aw2w = (const float*)d_in[21]; const float* aw2b = (const float*)d_in[22];
    const float* aw3w = (const float*)d_in[23]; const float* aw3b = (const float*)d_in[24];
    const float* op0w = (const float*)d_in[25]; const float* op0b = (const float*)d_in[26];
    const float* op1w = (const float*)d_in[27]; const float* op1b = (const float*)d_in[28];

    float *extra, *b192a, *value, *b64a, *b64b, *b64c, *b64d, *so, *aw, *attn;
    float *part, *part2, *part3;
    cudaGetSymbolAddress((void**)&extra, g_extra);
    cudaGetSymbolAddress((void**)&b192a, g_b192a);
    cudaGetSymbolAddress((void**)&value, g_value);
    cudaGetSymbolAddress((void**)&b64a,  g_b64a);
    cudaGetSymbolAddress((void**)&b64b,  g_b64b);
    cudaGetSymbolAddress((void**)&b64c,  g_b64c);
    cudaGetSymbolAddress((void**)&b64d,  g_b64d);
    cudaGetSymbolAddress((void**)&so,    g_so);
    cudaGetSymbolAddress((void**)&aw,    g_aw);
    cudaGetSymbolAddress((void**)&attn,  g_attn);
    cudaGetSymbolAddress((void**)&part,  g_part);
    cudaGetSymbolAddress((void**)&part2, g_part2);
    cudaGetSymbolAddress((void**)&part3, g_part3);

    // 1-2: preprocessing
    k_flows<<<4, 256>>>(f1, f2, ff1, ff2);                                   // 1
    k_warp<<<(7 * 8 * 1024 + 255) / 256, 256>>>(x);                          // 2
    // 3: head stage 0 (so0 + aw0 in one launch, 240 blocks)
    conv_dual(extra, so0w, so0b, nullptr, extra, aw0w, aw0b, nullptr,
              460, 64, 64, 1, 15, part2, part3);                             // 3
    // 4: vp0 (ncu capture position)
    conv_single(x, vp0w, vp0b, nullptr, nullptr, part, 192, 192, 1, 12);     // 4
    fin_dual(part2, so0b, b64a, part3, aw0b, b64c, 64, 1, 15);               // 5
    fin_single(part, vp0b, b192a, nullptr, 192, 1, 12);                      // 6
    // head stage 1
    conv_dual(b64a, so1w, so1b, nullptr, b64c, aw1w, aw1b, nullptr,
              64, 64, 64, 1, 8, part2, part3);                               // 7
    conv_single(b192a, vp1w, vp1b, nullptr, nullptr, part, 192, 192, 0, 12); // 8
    fin_dual(part2, so1b, b64b, part3, aw1b, b64d, 64, 1, 8);                // 9
    fin_single(part, vp1b, value, nullptr, 192, 0, 12);                      // 10
    // head stage 2
    conv_dual(b64b, so2w, so2b, nullptr, b64d, aw2w, aw2b, nullptr,
              64, 64, 64, 1, 8, part2, part3);                               // 11
    k_vperm<<<(24 * HW * 8 + 255) / 256, 256>>>();                           // 12
    fin_dual(part2, so2b, b64a, part3, aw2b, b64c, 64, 1, 8);                // 13
    // head stage 3 (so3 + aw3 in one launch, 1192 blocks, nz=1)
    conv_dual(b64a, so3w, so3b, so, b64c, aw3w, aw3b, aw,
              64, 1728, 7776, 0, 1, nullptr, nullptr);                       // 14
    // sampling with fused softmax
    k_sample<<<3072, 256>>>();                                               // 15
    // output projection + residual
    conv_single(attn, op0w, op0b, nullptr, nullptr, part, 192, 192, 1, 12);  // 16
    fin_single(part, op0b, b192a, nullptr, 192, 1, 12);                      // 17
    conv_single(b192a, op1w, op1b, nullptr, nullptr, part, 192, 192, 0, 12); // 18
    fin_single(part, op1b, (float*)d_out, x, 192, 0, 12);                    // 19
}